// round 2
// baseline (speedup 1.0000x reference)
#include <cuda_runtime.h>
#include <math.h>

#define T_LEN 1024
#define BATCH 64
#define DIN   256
#define HID   256
#define HID2  512
#define G4    1024
#define G8    2048

// ---------------- scratch (static device allocations only) ----------------
__device__ float g_xf[(size_t)T_LEN * G4 * BATCH];   // fwd gate inputs  [t][row][b]
__device__ float g_xb[(size_t)T_LEN * G4 * BATCH];   // bwd gate inputs  [t][row][b]
__device__ float g_xs[(size_t)T_LEN * G8 * BATCH];   // combiner gate inputs [t][row][b]
__device__ float g_hf[(size_t)T_LEN * HID * BATCH];  // fwd hidden history [t][u][b]
__device__ float g_hb[(size_t)T_LEN * HID * BATCH];  // bwd hidden history [t][u][b]
__device__ float g_hwf[2][HID * BATCH];              // fwd working h (double buffered) [u][b]
__device__ float g_hwb[2][HID * BATCH];
__device__ float g_hws[2][HID2 * BATCH];             // combiner working h [u][b]
__device__ unsigned g_bar[4];                        // spin barrier counters

__device__ __forceinline__ float sigf(float x) { return 1.0f / (1.0f + __expf(-x)); }
__device__ __forceinline__ float tanhfast(float x) { return 2.0f / (1.0f + __expf(-2.0f * x)) - 1.0f; }

// ---------------------------------------------------------------------------
// GEMM 1: gate inputs from x.
// out[t][r][b] = bias[r] + sum_k x[b][tsrc][k] * W[r][k],  tsrc = t or T-1-t
// Block: 128 rows x 64 batch, K loop in tiles of 16. 256 threads, 8x4 per thread.
// ---------------------------------------------------------------------------
__global__ void __launch_bounds__(256) gemm_in_kernel(
    const float* __restrict__ x, const float* __restrict__ W,
    const float* __restrict__ bias, float* __restrict__ out, int reversed)
{
    __shared__ float As[16 * 132];  // [k][r] padded
    __shared__ float Bs[16 * 68];   // [k][b] padded

    int t    = blockIdx.x;
    int tsrc = reversed ? (T_LEN - 1 - t) : t;
    int r0   = blockIdx.y * 128;
    int tid  = threadIdx.x;
    int tx   = tid & 15;   // batch quad
    int ty   = tid >> 4;   // row octet

    float acc[8][4];
#pragma unroll
    for (int i = 0; i < 8; i++)
#pragma unroll
        for (int j = 0; j < 4; j++) acc[i][j] = 0.0f;

    // W load mapping: row = (tid>>2) and (tid>>2)+64, col quad = tid&3 (coalesced)
    int wrow = tid >> 2;
    int wcq  = (tid & 3) * 4;
    // x load mapping: b = tid>>2, k quad = tid&3 (coalesced within each batch row)
    int lb = tid >> 2;
    int lk = (tid & 3) * 4;
    const float* xrow = x + (size_t)lb * T_LEN * DIN + (size_t)tsrc * DIN;

    for (int k0 = 0; k0 < DIN; k0 += 16) {
        float4 w0 = *reinterpret_cast<const float4*>(&W[(size_t)(r0 + wrow) * DIN + k0 + wcq]);
        float4 w1 = *reinterpret_cast<const float4*>(&W[(size_t)(r0 + wrow + 64) * DIN + k0 + wcq]);
        As[(wcq + 0) * 132 + wrow] = w0.x;
        As[(wcq + 1) * 132 + wrow] = w0.y;
        As[(wcq + 2) * 132 + wrow] = w0.z;
        As[(wcq + 3) * 132 + wrow] = w0.w;
        As[(wcq + 0) * 132 + wrow + 64] = w1.x;
        As[(wcq + 1) * 132 + wrow + 64] = w1.y;
        As[(wcq + 2) * 132 + wrow + 64] = w1.z;
        As[(wcq + 3) * 132 + wrow + 64] = w1.w;

        float4 xv = *reinterpret_cast<const float4*>(&xrow[k0 + lk]);
        Bs[(lk + 0) * 68 + lb] = xv.x;
        Bs[(lk + 1) * 68 + lb] = xv.y;
        Bs[(lk + 2) * 68 + lb] = xv.z;
        Bs[(lk + 3) * 68 + lb] = xv.w;
        __syncthreads();

#pragma unroll
        for (int k = 0; k < 16; k++) {
            float a[8];
#pragma unroll
            for (int i = 0; i < 8; i++) a[i] = As[k * 132 + ty * 8 + i];
            float b0 = Bs[k * 68 + tx * 4 + 0];
            float b1 = Bs[k * 68 + tx * 4 + 1];
            float b2 = Bs[k * 68 + tx * 4 + 2];
            float b3 = Bs[k * 68 + tx * 4 + 3];
#pragma unroll
            for (int i = 0; i < 8; i++) {
                acc[i][0] += a[i] * b0;
                acc[i][1] += a[i] * b1;
                acc[i][2] += a[i] * b2;
                acc[i][3] += a[i] * b3;
            }
        }
        __syncthreads();
    }

    float* op = out + (size_t)t * G4 * BATCH;
#pragma unroll
    for (int i = 0; i < 8; i++) {
        int r = r0 + ty * 8 + i;
        float bv = bias[r];
#pragma unroll
        for (int j = 0; j < 4; j++)
            op[(size_t)r * BATCH + tx * 4 + j] = acc[i][j] + bv;
    }
}

// ---------------------------------------------------------------------------
// GEMM 2: combiner gate inputs from concat(f, b) hidden histories.
// out[t][r][b] = bs[r] + sum_k comb[t][k][b] * Wis[r][k], K = 512
// comb[t][k][b] = g_hf[t][k][b] (k<256) else g_hb[t][k-256][b]  (already [k][b])
// ---------------------------------------------------------------------------
__global__ void __launch_bounds__(256) gemm_comb_kernel(
    const float* __restrict__ W, const float* __restrict__ bias, float* __restrict__ out)
{
    __shared__ float As[16 * 132];
    __shared__ float Bs[16 * 68];

    int t   = blockIdx.x;
    int r0  = blockIdx.y * 128;
    int tid = threadIdx.x;
    int tx  = tid & 15;
    int ty  = tid >> 4;

    float acc[8][4];
#pragma unroll
    for (int i = 0; i < 8; i++)
#pragma unroll
        for (int j = 0; j < 4; j++) acc[i][j] = 0.0f;

    int wrow = tid >> 2;
    int wcq  = (tid & 3) * 4;
    int kl = tid >> 4;        // k row within tile (0..15)
    int b4 = (tid & 15) * 4;  // batch quad

    const float* hfp = g_hf + (size_t)t * HID * BATCH;
    const float* hbp = g_hb + (size_t)t * HID * BATCH;

    for (int k0 = 0; k0 < HID2; k0 += 16) {
        float4 w0 = *reinterpret_cast<const float4*>(&W[(size_t)(r0 + wrow) * HID2 + k0 + wcq]);
        float4 w1 = *reinterpret_cast<const float4*>(&W[(size_t)(r0 + wrow + 64) * HID2 + k0 + wcq]);
        As[(wcq + 0) * 132 + wrow] = w0.x;
        As[(wcq + 1) * 132 + wrow] = w0.y;
        As[(wcq + 2) * 132 + wrow] = w0.z;
        As[(wcq + 3) * 132 + wrow] = w0.w;
        As[(wcq + 0) * 132 + wrow + 64] = w1.x;
        As[(wcq + 1) * 132 + wrow + 64] = w1.y;
        As[(wcq + 2) * 132 + wrow + 64] = w1.z;
        As[(wcq + 3) * 132 + wrow + 64] = w1.w;

        int gk = k0 + kl;
        const float* src = (gk < HID) ? (hfp + (size_t)gk * BATCH)
                                      : (hbp + (size_t)(gk - HID) * BATCH);
        float4 hv = *reinterpret_cast<const float4*>(src + b4);
        Bs[kl * 68 + b4 + 0] = hv.x;
        Bs[kl * 68 + b4 + 1] = hv.y;
        Bs[kl * 68 + b4 + 2] = hv.z;
        Bs[kl * 68 + b4 + 3] = hv.w;
        __syncthreads();

#pragma unroll
        for (int k = 0; k < 16; k++) {
            float a[8];
#pragma unroll
            for (int i = 0; i < 8; i++) a[i] = As[k * 132 + ty * 8 + i];
            float b0 = Bs[k * 68 + tx * 4 + 0];
            float b1 = Bs[k * 68 + tx * 4 + 1];
            float b2 = Bs[k * 68 + tx * 4 + 2];
            float b3 = Bs[k * 68 + tx * 4 + 3];
#pragma unroll
            for (int i = 0; i < 8; i++) {
                acc[i][0] += a[i] * b0;
                acc[i][1] += a[i] * b1;
                acc[i][2] += a[i] * b2;
                acc[i][3] += a[i] * b3;
            }
        }
        __syncthreads();
    }

    float* op = out + (size_t)t * G8 * BATCH;
#pragma unroll
    for (int i = 0; i < 8; i++) {
        int r = r0 + ty * 8 + i;
        float bv = bias[r];
#pragma unroll
        for (int j = 0; j < 4; j++)
            op[(size_t)r * BATCH + tx * 4 + j] = acc[i][j] + bv;
    }
}

// ---------------------------------------------------------------------------
// Persistent fwd+bwd LSTM scan. 128 CTAs (64 per direction), all co-resident.
// Each CTA owns 4 hidden units: computes 4 gates x 4 units x 64 batch per step.
// h shared via L2 (double-buffered), one spin barrier per step per direction.
// Thread t: batch b = t&63, unit-in-group ug = t>>6 -> exactly one (u,b) cell.
// ---------------------------------------------------------------------------
__global__ void __launch_bounds__(256) scan_fb_kernel(
    const float* __restrict__ Whf, const float* __restrict__ Whb)
{
    extern __shared__ float sm[];
    float* Wsm = sm;               // [16][HID]   16 KB
    float* Hsm = sm + 16 * HID;    // [HID][64]   64 KB

    int cta = blockIdx.x;
    int dir = cta >> 6;
    int grp = cta & 63;
    const float* Wh  = dir ? Whb : Whf;
    const float* Xin = dir ? g_xb : g_xf;
    float* hist = dir ? g_hb : g_hf;
    float* hw0  = dir ? g_hwb[0] : g_hwf[0];
    float* hw1  = dir ? g_hwb[1] : g_hwf[1];
    unsigned* bar = &g_bar[dir];

    int tid = threadIdx.x;
    int b  = tid & 63;
    int ug = tid >> 6;
    int u0 = grp * 4;
    int u  = u0 + ug;

    // cache this CTA's 16 weight rows (4 gates of 4 units), row-major [lr][k]
    for (int i = tid; i < 16 * HID; i += 256) {
        int lr = i >> 8;          // /256
        int k  = i & 255;
        int gate = lr >> 2, uu = lr & 3;
        Wsm[lr * HID + k] = Wh[(size_t)(gate * HID + u0 + uu) * HID + k];
    }
    __syncthreads();

    const float* wI = &Wsm[(0 * 4 + ug) * HID];
    const float* wF = &Wsm[(1 * 4 + ug) * HID];
    const float* wG = &Wsm[(2 * 4 + ug) * HID];
    const float* wO = &Wsm[(3 * 4 + ug) * HID];

    float c = 0.0f;
    for (int t = 0; t < T_LEN; t++) {
        const float* xt = Xin + (size_t)t * G4 * BATCH;
        float gi = xt[(0 * HID + u) * BATCH + b];
        float gf = xt[(1 * HID + u) * BATCH + b];
        float gg = xt[(2 * HID + u) * BATCH + b];
        float go = xt[(3 * HID + u) * BATCH + b];

        if (t > 0) {
            // stage full h (written by all CTAs last step) into SMEM via L2
            const float4* src = reinterpret_cast<const float4*>((t & 1) ? hw0 : hw1);
            float4* dst = reinterpret_cast<float4*>(Hsm);
            for (int i = tid; i < HID * BATCH / 4; i += 256) dst[i] = __ldcg(src + i);
            __syncthreads();
#pragma unroll 4
            for (int k = 0; k < HID; k++) {
                float hv = Hsm[k * BATCH + b];
                gi += wI[k] * hv;
                gf += wF[k] * hv;
                gg += wG[k] * hv;
                go += wO[k] * hv;
            }
        }

        float ig = sigf(gi), fg = sigf(gf), og = sigf(go);
        float gt = tanhfast(gg);
        c = fg * c + ig * gt;
        float h = og * tanhfast(c);

        float* hw_w = (t & 1) ? hw1 : hw0;
        hw_w[u * BATCH + b] = h;
        hist[(size_t)t * HID * BATCH + u * BATCH + b] = h;

        __syncthreads();
        if (tid == 0) {
            __threadfence();
            atomicAdd(bar, 1u);
            unsigned target = (unsigned)(t + 1) * 64u;
            while (*((volatile unsigned*)bar) < target) { }
        }
        __syncthreads();
    }
}

// ---------------------------------------------------------------------------
// Persistent combiner LSTM scan. 128 CTAs, each owns 4 of the 512 hidden units.
// K = 512, gates = Xs[t] + Whs @ h. Only the final h matters downstream.
// ---------------------------------------------------------------------------
__global__ void __launch_bounds__(256) scan_comb_kernel(const float* __restrict__ Whs)
{
    extern __shared__ float sm[];
    float* Wsm = sm;                // [16][512]  32 KB
    float* Hsm = sm + 16 * HID2;    // [512][64] 128 KB

    int cta = blockIdx.x;
    int tid = threadIdx.x;
    int b  = tid & 63;
    int ug = tid >> 6;
    int u0 = cta * 4;
    int u  = u0 + ug;
    unsigned* bar = &g_bar[2];

    for (int i = tid; i < 16 * HID2; i += 256) {
        int lr = i >> 9;          // /512
        int k  = i & 511;
        int gate = lr >> 2, uu = lr & 3;
        Wsm[lr * HID2 + k] = Whs[(size_t)(gate * HID2 + u0 + uu) * HID2 + k];
    }
    __syncthreads();

    const float* wI = &Wsm[(0 * 4 + ug) * HID2];
    const float* wF = &Wsm[(1 * 4 + ug) * HID2];
    const float* wG = &Wsm[(2 * 4 + ug) * HID2];
    const float* wO = &Wsm[(3 * 4 + ug) * HID2];

    float c = 0.0f;
    for (int t = 0; t < T_LEN; t++) {
        const float* xt = g_xs + (size_t)t * G8 * BATCH;
        float gi = xt[(0 * HID2 + u) * BATCH + b];
        float gf = xt[(1 * HID2 + u) * BATCH + b];
        float gg = xt[(2 * HID2 + u) * BATCH + b];
        float go = xt[(3 * HID2 + u) * BATCH + b];

        if (t > 0) {
            const float4* src = reinterpret_cast<const float4*>((t & 1) ? g_hws[0] : g_hws[1]);
            float4* dst = reinterpret_cast<float4*>(Hsm);
            for (int i = tid; i < HID2 * BATCH / 4; i += 256) dst[i] = __ldcg(src + i);
            __syncthreads();
#pragma unroll 4
            for (int k = 0; k < HID2; k++) {
                float hv = Hsm[k * BATCH + b];
                gi += wI[k] * hv;
                gf += wF[k] * hv;
                gg += wG[k] * hv;
                go += wO[k] * hv;
            }
        }

        float ig = sigf(gi), fg = sigf(gf), og = sigf(go);
        float gt = tanhfast(gg);
        c = fg * c + ig * gt;
        float h = og * tanhfast(c);

        float* hw_w = (t & 1) ? g_hws[1] : g_hws[0];
        hw_w[u * BATCH + b] = h;

        __syncthreads();
        if (tid == 0) {
            __threadfence();
            atomicAdd(bar, 1u);
            unsigned target = (unsigned)(t + 1) * 128u;
            while (*((volatile unsigned*)bar) < target) { }
        }
        __syncthreads();
    }
}

// ---------------------------------------------------------------------------
// Output head: out[b][l] = sigmoid(bo[l] + sum_k h_final[k][b] * Wo[l][k])
// Final combiner h lives in g_hws[1] (t = 1023 is odd).
// ---------------------------------------------------------------------------
__global__ void __launch_bounds__(128) head_kernel(
    const float* __restrict__ Wo, const float* __restrict__ bo, float* __restrict__ out)
{
    int tid = threadIdx.x;
    int l = tid >> 6;
    int b = tid & 63;
    const float* h = g_hws[1];
    float s = bo[l];
#pragma unroll 4
    for (int k = 0; k < HID2; k++)
        s += h[k * BATCH + b] * Wo[(size_t)l * HID2 + k];
    out[b * 2 + l] = 1.0f / (1.0f + __expf(-s));
}

// ---------------------------------------------------------------------------
extern "C" void kernel_launch(void* const* d_in, const int* in_sizes, int n_in,
                              void* d_out, int out_size)
{
    const float* x   = (const float*)d_in[0];
    const float* Wif = (const float*)d_in[1];
    const float* Whf = (const float*)d_in[2];
    const float* bf  = (const float*)d_in[3];
    const float* Wib = (const float*)d_in[4];
    const float* Whb = (const float*)d_in[5];
    const float* bb  = (const float*)d_in[6];
    const float* Wis = (const float*)d_in[7];
    const float* Whs = (const float*)d_in[8];
    const float* bs  = (const float*)d_in[9];
    const float* Wo  = (const float*)d_in[10];
    const float* bo  = (const float*)d_in[11];
    float* out = (float*)d_out;

    void *p_bar = nullptr, *p_xf = nullptr, *p_xb = nullptr, *p_xs = nullptr;
    cudaGetSymbolAddress(&p_bar, g_bar);
    cudaGetSymbolAddress(&p_xf, g_xf);
    cudaGetSymbolAddress(&p_xb, g_xb);
    cudaGetSymbolAddress(&p_xs, g_xs);

    const int SMEM_FB   = (16 * HID + HID * BATCH) * (int)sizeof(float);     //  80 KB
    const int SMEM_COMB = (16 * HID2 + HID2 * BATCH) * (int)sizeof(float);   // 160 KB
    cudaFuncSetAttribute(scan_fb_kernel, cudaFuncAttributeMaxDynamicSharedMemorySize, SMEM_FB);
    cudaFuncSetAttribute(scan_comb_kernel, cudaFuncAttributeMaxDynamicSharedMemorySize, SMEM_COMB);

    // reset spin-barrier counters (graph-captured, deterministic per replay)
    cudaMemsetAsync(p_bar, 0, sizeof(unsigned) * 4, 0);

    // 1) input-side gate GEMMs (fwd + bwd)
    gemm_in_kernel<<<dim3(T_LEN, G4 / 128), 256>>>(x, Wif, bf, (float*)p_xf, 0);
    gemm_in_kernel<<<dim3(T_LEN, G4 / 128), 256>>>(x, Wib, bb, (float*)p_xb, 1);

    // 2) fwd + bwd recurrent scans (persistent, 128 co-resident CTAs)
    scan_fb_kernel<<<128, 256, SMEM_FB>>>(Whf, Whb);

    // 3) combiner input GEMM over all timesteps
    gemm_comb_kernel<<<dim3(T_LEN, G8 / 128), 256>>>(Wis, bs, (float*)p_xs);

    // 4) combiner recurrent scan
    scan_comb_kernel<<<128, 256, SMEM_COMB>>>(Whs);

    // 5) output head
    head_kernel<<<1, 128>>>(Wo, bo, out);
}

// round 6
// speedup vs baseline: 1.1196x; 1.1196x over previous
#include <cuda_runtime.h>
#include <cuda_bf16.h>
#include <cstdint>
#include <math.h>

#define T_LEN 1024
#define BATCH 64
#define DIN   256
#define HID   256
#define HID2  512
#define G4    1024
#define G8    2048

// ---------------- scratch (static device allocations only) ----------------
__device__ float g_xf[(size_t)T_LEN * G4 * BATCH];   // fwd gate inputs  [t][row][b]
__device__ float g_xb[(size_t)T_LEN * G4 * BATCH];   // bwd gate inputs  [t][row][b]
__device__ float g_xs[(size_t)T_LEN * G8 * BATCH];   // combiner gate inputs [t][row][b]
__device__ float g_hf[(size_t)T_LEN * HID * BATCH];  // fwd hidden history [t][u][b]
__device__ float g_hb[(size_t)T_LEN * HID * BATCH];  // bwd hidden history [t][u][b]
__device__ float g_hwf[2][HID * BATCH];              // fwd working h (double buffered) [u][b]
__device__ float g_hwb[2][HID * BATCH];
__device__ float g_hws[2][HID2 * BATCH];             // combiner working h [u][b]
__device__ unsigned g_bar[4];                        // spin barrier counters

// bf16 hi/lo split buffers for tensor-core GEMMs
__device__ __nv_bfloat16 g_xh[(size_t)BATCH * T_LEN * DIN];
__device__ __nv_bfloat16 g_xl[(size_t)BATCH * T_LEN * DIN];
__device__ __nv_bfloat16 g_wifh[G4 * DIN], g_wifl[G4 * DIN];
__device__ __nv_bfloat16 g_wibh[G4 * DIN], g_wibl[G4 * DIN];
__device__ __nv_bfloat16 g_wish[G8 * HID2], g_wisl[G8 * HID2];
__device__ __nv_bfloat16 g_cth[(size_t)T_LEN * BATCH * HID2];  // combined f/b hist [t][b][k] hi
__device__ __nv_bfloat16 g_ctl[(size_t)T_LEN * BATCH * HID2];  // lo

__device__ __forceinline__ float sigf(float x) { return 1.0f / (1.0f + __expf(-x)); }
__device__ __forceinline__ float tanhfast(float x) { return 2.0f / (1.0f + __expf(-2.0f * x)) - 1.0f; }

// ---------------------------------------------------------------------------
// mma.sync m16n8k16 bf16 -> fp32 (supported at plain sm_100 PTX target)
// ---------------------------------------------------------------------------
__device__ __forceinline__ void mma16816(float* c, const uint32_t* a, const uint32_t* b) {
    asm volatile(
        "mma.sync.aligned.m16n8k16.row.col.f32.bf16.bf16.f32 "
        "{%0,%1,%2,%3}, {%4,%5,%6,%7}, {%8,%9}, {%0,%1,%2,%3};"
        : "+f"(c[0]), "+f"(c[1]), "+f"(c[2]), "+f"(c[3])
        : "r"(a[0]), "r"(a[1]), "r"(a[2]), "r"(a[3]), "r"(b[0]), "r"(b[1]));
}

// ---------------------------------------------------------------------------
// Prep: fp32 -> (bf16 hi, bf16 lo) split, vectorized 4 elements/thread.
// n must be a multiple of 4 (all our sizes are).
// ---------------------------------------------------------------------------
__global__ void convert_split_kernel(const float* __restrict__ s,
                                     __nv_bfloat16* __restrict__ h,
                                     __nv_bfloat16* __restrict__ l, int n4)
{
    int i = blockIdx.x * blockDim.x + threadIdx.x;
    if (i < n4) {
        float4 v = reinterpret_cast<const float4*>(s)[i];
        __nv_bfloat16 h0 = __float2bfloat16(v.x);
        __nv_bfloat16 h1 = __float2bfloat16(v.y);
        __nv_bfloat16 h2 = __float2bfloat16(v.z);
        __nv_bfloat16 h3 = __float2bfloat16(v.w);
        __nv_bfloat162 hp0 = __nv_bfloat162(h0, h1);
        __nv_bfloat162 hp1 = __nv_bfloat162(h2, h3);
        __nv_bfloat162 lp0 = __nv_bfloat162(__float2bfloat16(v.x - __bfloat162float(h0)),
                                            __float2bfloat16(v.y - __bfloat162float(h1)));
        __nv_bfloat162 lp1 = __nv_bfloat162(__float2bfloat16(v.z - __bfloat162float(h2)),
                                            __float2bfloat16(v.w - __bfloat162float(h3)));
        reinterpret_cast<__nv_bfloat162*>(h)[i * 2 + 0] = hp0;
        reinterpret_cast<__nv_bfloat162*>(h)[i * 2 + 1] = hp1;
        reinterpret_cast<__nv_bfloat162*>(l)[i * 2 + 0] = lp0;
        reinterpret_cast<__nv_bfloat162*>(l)[i * 2 + 1] = lp1;
    }
}

// ---------------------------------------------------------------------------
// Prep: transpose f/b hidden histories [t][k][b] fp32 -> combT [t][b][512] bf16 hi/lo
// ---------------------------------------------------------------------------
__global__ void __launch_bounds__(256) transpose_comb_kernel()
{
    __shared__ float tile[64][65];
    int t = blockIdx.x, kb = blockIdx.y;
    int k0 = kb * 64;
    const float* src = (k0 < HID) ? (g_hf + (size_t)t * HID * BATCH + (size_t)k0 * BATCH)
                                  : (g_hb + (size_t)t * HID * BATCH + (size_t)(k0 - HID) * BATCH);
    int tid = threadIdx.x;
    for (int i = tid; i < 4096; i += 256) {
        int kk = i >> 6, b = i & 63;
        tile[kk][b] = src[(size_t)kk * BATCH + b];
    }
    __syncthreads();
    for (int i = tid; i < 4096; i += 256) {
        int b = i >> 6, kk = i & 63;
        float v = tile[kk][b];
        __nv_bfloat16 h = __float2bfloat16(v);
        __nv_bfloat16 l = __float2bfloat16(v - __bfloat162float(h));
        size_t o = ((size_t)t * BATCH + b) * HID2 + k0 + kk;
        g_cth[o] = h;
        g_ctl[o] = l;
    }
}

// ---------------------------------------------------------------------------
// Tensor-core GEMM via mma.sync (bf16 hi/lo 3-pass split, fp32 accum).
//   out[t][r][b] = bias[r] + sum_k W[r][k] * Bsrc[t][b][k]
// Grid: (T_LEN, M/128). Block 256 = 8 warps in 4x2; each warp 32 rows x 32 b.
// K staged in 64-wide smem chunks (hi+lo for A and B; stride 72 for
// conflict-free b32 fragment loads). Passes: Ah*Bh + Ah*Bl + Al*Bh.
// xmode=1: B row b from x layout [b][1024][256] at tsrc; xmode=0: combT.
// ---------------------------------------------------------------------------
#define SMEM_STRIDE 72
__global__ void __launch_bounds__(256) mma_gemm_kernel(
    const __nv_bfloat16* __restrict__ Wh, const __nv_bfloat16* __restrict__ Wl,
    const __nv_bfloat16* __restrict__ Bh, const __nv_bfloat16* __restrict__ Bl,
    const float* __restrict__ bias, float* __restrict__ out,
    int K, int xmode, int reversed, int nrows)
{
    extern __shared__ __nv_bfloat16 smem[];
    __nv_bfloat16* sAh = smem;                        // [128][72]
    __nv_bfloat16* sAl = smem + 128 * SMEM_STRIDE;    // [128][72]
    __nv_bfloat16* sBh = smem + 256 * SMEM_STRIDE;    // [64][72]
    __nv_bfloat16* sBl = smem + 320 * SMEM_STRIDE;    // [64][72]

    int t   = blockIdx.x;
    int r0  = blockIdx.y * 128;
    int tid = threadIdx.x;
    int wid = tid >> 5, lane = tid & 31;
    int wm = (wid & 3) * 32;     // warp row offset within 128
    int wn = (wid >> 2) * 32;    // warp batch offset within 64

    size_t bbase, bstride;
    if (xmode) {
        int tsrc = reversed ? (T_LEN - 1 - t) : t;
        bbase   = (size_t)tsrc * DIN;
        bstride = (size_t)T_LEN * DIN;
    } else {
        bbase   = (size_t)t * BATCH * HID2;
        bstride = HID2;
    }

    float acc[2][4][4];
#pragma unroll
    for (int mi = 0; mi < 2; mi++)
#pragma unroll
        for (int ni = 0; ni < 4; ni++)
#pragma unroll
            for (int j = 0; j < 4; j++) acc[mi][ni][j] = 0.0f;

    int q = lane >> 2;           // 0..7
    int p2 = (lane & 3) * 2;     // 0,2,4,6

    for (int k0 = 0; k0 < K; k0 += 64) {
        // ---- stage A hi/lo: 128 rows x 64 k each, uint4 = 8 bf16
        for (int idx = tid; idx < 1024; idx += 256) {
            int row = idx >> 3, u = idx & 7;
            const __nv_bfloat16* s0 = Wh + (size_t)(r0 + row) * K + k0 + u * 8;
            const __nv_bfloat16* s1 = Wl + (size_t)(r0 + row) * K + k0 + u * 8;
            *reinterpret_cast<uint4*>(sAh + row * SMEM_STRIDE + u * 8) = *reinterpret_cast<const uint4*>(s0);
            *reinterpret_cast<uint4*>(sAl + row * SMEM_STRIDE + u * 8) = *reinterpret_cast<const uint4*>(s1);
        }
        // ---- stage B hi/lo: 64 rows (batch) x 64 k each
        for (int idx = tid; idx < 512; idx += 256) {
            int row = idx >> 3, u = idx & 7;
            const __nv_bfloat16* s0 = Bh + bbase + (size_t)row * bstride + k0 + u * 8;
            const __nv_bfloat16* s1 = Bl + bbase + (size_t)row * bstride + k0 + u * 8;
            *reinterpret_cast<uint4*>(sBh + row * SMEM_STRIDE + u * 8) = *reinterpret_cast<const uint4*>(s0);
            *reinterpret_cast<uint4*>(sBl + row * SMEM_STRIDE + u * 8) = *reinterpret_cast<const uint4*>(s1);
        }
        __syncthreads();

#pragma unroll
        for (int ks = 0; ks < 4; ks++) {
            int kb = ks * 16;
            uint32_t ah[2][4], al[2][4], bh[4][2], bl[4][2];
#pragma unroll
            for (int mi = 0; mi < 2; mi++) {
                int rlo = wm + mi * 16 + q;
                ah[mi][0] = *reinterpret_cast<const uint32_t*>(sAh + rlo * SMEM_STRIDE + kb + p2);
                ah[mi][1] = *reinterpret_cast<const uint32_t*>(sAh + (rlo + 8) * SMEM_STRIDE + kb + p2);
                ah[mi][2] = *reinterpret_cast<const uint32_t*>(sAh + rlo * SMEM_STRIDE + kb + 8 + p2);
                ah[mi][3] = *reinterpret_cast<const uint32_t*>(sAh + (rlo + 8) * SMEM_STRIDE + kb + 8 + p2);
                al[mi][0] = *reinterpret_cast<const uint32_t*>(sAl + rlo * SMEM_STRIDE + kb + p2);
                al[mi][1] = *reinterpret_cast<const uint32_t*>(sAl + (rlo + 8) * SMEM_STRIDE + kb + p2);
                al[mi][2] = *reinterpret_cast<const uint32_t*>(sAl + rlo * SMEM_STRIDE + kb + 8 + p2);
                al[mi][3] = *reinterpret_cast<const uint32_t*>(sAl + (rlo + 8) * SMEM_STRIDE + kb + 8 + p2);
            }
#pragma unroll
            for (int ni = 0; ni < 4; ni++) {
                int n = wn + ni * 8 + q;
                bh[ni][0] = *reinterpret_cast<const uint32_t*>(sBh + n * SMEM_STRIDE + kb + p2);
                bh[ni][1] = *reinterpret_cast<const uint32_t*>(sBh + n * SMEM_STRIDE + kb + 8 + p2);
                bl[ni][0] = *reinterpret_cast<const uint32_t*>(sBl + n * SMEM_STRIDE + kb + p2);
                bl[ni][1] = *reinterpret_cast<const uint32_t*>(sBl + n * SMEM_STRIDE + kb + 8 + p2);
            }
#pragma unroll
            for (int mi = 0; mi < 2; mi++)
#pragma unroll
                for (int ni = 0; ni < 4; ni++) {
                    mma16816(acc[mi][ni], ah[mi], bh[ni]);
                    mma16816(acc[mi][ni], ah[mi], bl[ni]);
                    mma16816(acc[mi][ni], al[mi], bh[ni]);
                }
        }
        __syncthreads();
    }

    // ---- epilogue: c0,c1 at (row, col..col+1); c2,c3 at (row+8, col..col+1)
    float* op = out + (size_t)t * nrows * BATCH;
#pragma unroll
    for (int mi = 0; mi < 2; mi++) {
        int rA = r0 + wm + mi * 16 + q;
        int rB = rA + 8;
        float bvA = bias[rA], bvB = bias[rB];
#pragma unroll
        for (int ni = 0; ni < 4; ni++) {
            int col = wn + ni * 8 + p2;
            float2 vA = make_float2(acc[mi][ni][0] + bvA, acc[mi][ni][1] + bvA);
            float2 vB = make_float2(acc[mi][ni][2] + bvB, acc[mi][ni][3] + bvB);
            *reinterpret_cast<float2*>(op + (size_t)rA * BATCH + col) = vA;
            *reinterpret_cast<float2*>(op + (size_t)rB * BATCH + col) = vB;
        }
    }
}

// ---------------------------------------------------------------------------
// Persistent fwd+bwd LSTM scan. 128 CTAs (64 per direction), all co-resident.
// (unchanged from passing round-1 kernel)
// ---------------------------------------------------------------------------
__global__ void __launch_bounds__(256) scan_fb_kernel(
    const float* __restrict__ Whf, const float* __restrict__ Whb)
{
    extern __shared__ float sm[];
    float* Wsm = sm;               // [16][HID]   16 KB
    float* Hsm = sm + 16 * HID;    // [HID][64]   64 KB

    int cta = blockIdx.x;
    int dir = cta >> 6;
    int grp = cta & 63;
    const float* Wh  = dir ? Whb : Whf;
    const float* Xin = dir ? g_xb : g_xf;
    float* hist = dir ? g_hb : g_hf;
    float* hw0  = dir ? g_hwb[0] : g_hwf[0];
    float* hw1  = dir ? g_hwb[1] : g_hwf[1];
    unsigned* bar = &g_bar[dir];

    int tid = threadIdx.x;
    int b  = tid & 63;
    int ug = tid >> 6;
    int u0 = grp * 4;
    int u  = u0 + ug;

    for (int i = tid; i < 16 * HID; i += 256) {
        int lr = i >> 8;
        int k  = i & 255;
        int gate = lr >> 2, uu = lr & 3;
        Wsm[lr * HID + k] = Wh[(size_t)(gate * HID + u0 + uu) * HID + k];
    }
    __syncthreads();

    const float* wI = &Wsm[(0 * 4 + ug) * HID];
    const float* wF = &Wsm[(1 * 4 + ug) * HID];
    const float* wG = &Wsm[(2 * 4 + ug) * HID];
    const float* wO = &Wsm[(3 * 4 + ug) * HID];

    float c = 0.0f;
    for (int t = 0; t < T_LEN; t++) {
        const float* xt = Xin + (size_t)t * G4 * BATCH;
        float gi = xt[(0 * HID + u) * BATCH + b];
        float gf = xt[(1 * HID + u) * BATCH + b];
        float gg = xt[(2 * HID + u) * BATCH + b];
        float go = xt[(3 * HID + u) * BATCH + b];

        if (t > 0) {
            const float4* src = reinterpret_cast<const float4*>((t & 1) ? hw0 : hw1);
            float4* dst = reinterpret_cast<float4*>(Hsm);
            for (int i = tid; i < HID * BATCH / 4; i += 256) dst[i] = __ldcg(src + i);
            __syncthreads();
#pragma unroll 4
            for (int k = 0; k < HID; k++) {
                float hv = Hsm[k * BATCH + b];
                gi += wI[k] * hv;
                gf += wF[k] * hv;
                gg += wG[k] * hv;
                go += wO[k] * hv;
            }
        }

        float ig = sigf(gi), fg = sigf(gf), og = sigf(go);
        float gt = tanhfast(gg);
        c = fg * c + ig * gt;
        float h = og * tanhfast(c);

        float* hw_w = (t & 1) ? hw1 : hw0;
        hw_w[u * BATCH + b] = h;
        hist[(size_t)t * HID * BATCH + u * BATCH + b] = h;

        __syncthreads();
        if (tid == 0) {
            __threadfence();
            atomicAdd(bar, 1u);
            unsigned target = (unsigned)(t + 1) * 64u;
            while (*((volatile unsigned*)bar) < target) { }
        }
        __syncthreads();
    }
}

// ---------------------------------------------------------------------------
// Persistent combiner LSTM scan. (unchanged from passing round-1 kernel)
// ---------------------------------------------------------------------------
__global__ void __launch_bounds__(256) scan_comb_kernel(const float* __restrict__ Whs)
{
    extern __shared__ float sm[];
    float* Wsm = sm;                // [16][512]  32 KB
    float* Hsm = sm + 16 * HID2;    // [512][64] 128 KB

    int cta = blockIdx.x;
    int tid = threadIdx.x;
    int b  = tid & 63;
    int ug = tid >> 6;
    int u0 = cta * 4;
    int u  = u0 + ug;
    unsigned* bar = &g_bar[2];

    for (int i = tid; i < 16 * HID2; i += 256) {
        int lr = i >> 9;
        int k  = i & 511;
        int gate = lr >> 2, uu = lr & 3;
        Wsm[lr * HID2 + k] = Whs[(size_t)(gate * HID2 + u0 + uu) * HID2 + k];
    }
    __syncthreads();

    const float* wI = &Wsm[(0 * 4 + ug) * HID2];
    const float* wF = &Wsm[(1 * 4 + ug) * HID2];
    const float* wG = &Wsm[(2 * 4 + ug) * HID2];
    const float* wO = &Wsm[(3 * 4 + ug) * HID2];

    float c = 0.0f;
    for (int t = 0; t < T_LEN; t++) {
        const float* xt = g_xs + (size_t)t * G8 * BATCH;
        float gi = xt[(0 * HID2 + u) * BATCH + b];
        float gf = xt[(1 * HID2 + u) * BATCH + b];
        float gg = xt[(2 * HID2 + u) * BATCH + b];
        float go = xt[(3 * HID2 + u) * BATCH + b];

        if (t > 0) {
            const float4* src = reinterpret_cast<const float4*>((t & 1) ? g_hws[0] : g_hws[1]);
            float4* dst = reinterpret_cast<float4*>(Hsm);
            for (int i = tid; i < HID2 * BATCH / 4; i += 256) dst[i] = __ldcg(src + i);
            __syncthreads();
#pragma unroll 4
            for (int k = 0; k < HID2; k++) {
                float hv = Hsm[k * BATCH + b];
                gi += wI[k] * hv;
                gf += wF[k] * hv;
                gg += wG[k] * hv;
                go += wO[k] * hv;
            }
        }

        float ig = sigf(gi), fg = sigf(gf), og = sigf(go);
        float gt = tanhfast(gg);
        c = fg * c + ig * gt;
        float h = og * tanhfast(c);

        float* hw_w = (t & 1) ? g_hws[1] : g_hws[0];
        hw_w[u * BATCH + b] = h;

        __syncthreads();
        if (tid == 0) {
            __threadfence();
            atomicAdd(bar, 1u);
            unsigned target = (unsigned)(t + 1) * 128u;
            while (*((volatile unsigned*)bar) < target) { }
        }
        __syncthreads();
    }
}

// ---------------------------------------------------------------------------
// Output head (unchanged)
// ---------------------------------------------------------------------------
__global__ void __launch_bounds__(128) head_kernel(
    const float* __restrict__ Wo, const float* __restrict__ bo, float* __restrict__ out)
{
    int tid = threadIdx.x;
    int l = tid >> 6;
    int b = tid & 63;
    const float* h = g_hws[1];
    float s = bo[l];
#pragma unroll 4
    for (int k = 0; k < HID2; k++)
        s += h[k * BATCH + b] * Wo[(size_t)l * HID2 + k];
    out[b * 2 + l] = 1.0f / (1.0f + __expf(-s));
}

// ---------------------------------------------------------------------------
extern "C" void kernel_launch(void* const* d_in, const int* in_sizes, int n_in,
                              void* d_out, int out_size)
{
    const float* x   = (const float*)d_in[0];
    const float* Wif = (const float*)d_in[1];
    const float* Whf = (const float*)d_in[2];
    const float* bf  = (const float*)d_in[3];
    const float* Wib = (const float*)d_in[4];
    const float* Whb = (const float*)d_in[5];
    const float* bb  = (const float*)d_in[6];
    const float* Wis = (const float*)d_in[7];
    const float* Whs = (const float*)d_in[8];
    const float* bs  = (const float*)d_in[9];
    const float* Wo  = (const float*)d_in[10];
    const float* bo  = (const float*)d_in[11];
    float* out = (float*)d_out;

    void *p_bar, *p_xf, *p_xb, *p_xs;
    void *p_xh, *p_xl, *p_wifh, *p_wifl, *p_wibh, *p_wibl, *p_wish, *p_wisl, *p_cth, *p_ctl;
    cudaGetSymbolAddress(&p_bar, g_bar);
    cudaGetSymbolAddress(&p_xf, g_xf);
    cudaGetSymbolAddress(&p_xb, g_xb);
    cudaGetSymbolAddress(&p_xs, g_xs);
    cudaGetSymbolAddress(&p_xh, g_xh);
    cudaGetSymbolAddress(&p_xl, g_xl);
    cudaGetSymbolAddress(&p_wifh, g_wifh);
    cudaGetSymbolAddress(&p_wifl, g_wifl);
    cudaGetSymbolAddress(&p_wibh, g_wibh);
    cudaGetSymbolAddress(&p_wibl, g_wibl);
    cudaGetSymbolAddress(&p_wish, g_wish);
    cudaGetSymbolAddress(&p_wisl, g_wisl);
    cudaGetSymbolAddress(&p_cth, g_cth);
    cudaGetSymbolAddress(&p_ctl, g_ctl);

    const int SMEM_FB   = (16 * HID + HID * BATCH) * (int)sizeof(float);     //  80 KB
    const int SMEM_COMB = (16 * HID2 + HID2 * BATCH) * (int)sizeof(float);   // 160 KB
    const int SMEM_MMA  = 384 * SMEM_STRIDE * (int)sizeof(__nv_bfloat16);    //  55.3 KB
    cudaFuncSetAttribute(scan_fb_kernel, cudaFuncAttributeMaxDynamicSharedMemorySize, SMEM_FB);
    cudaFuncSetAttribute(scan_comb_kernel, cudaFuncAttributeMaxDynamicSharedMemorySize, SMEM_COMB);
    cudaFuncSetAttribute(mma_gemm_kernel, cudaFuncAttributeMaxDynamicSharedMemorySize, SMEM_MMA);

    cudaMemsetAsync(p_bar, 0, sizeof(unsigned) * 4, 0);

    // 0) bf16 hi/lo splits of x and weight matrices (vectorized x4)
    {
        int n4 = (BATCH * T_LEN * DIN) / 4;
        convert_split_kernel<<<(n4 + 255) / 256, 256>>>(x, (__nv_bfloat16*)p_xh, (__nv_bfloat16*)p_xl, n4);
        n4 = (G4 * DIN) / 4;
        convert_split_kernel<<<(n4 + 255) / 256, 256>>>(Wif, (__nv_bfloat16*)p_wifh, (__nv_bfloat16*)p_wifl, n4);
        convert_split_kernel<<<(n4 + 255) / 256, 256>>>(Wib, (__nv_bfloat16*)p_wibh, (__nv_bfloat16*)p_wibl, n4);
        n4 = (G8 * HID2) / 4;
        convert_split_kernel<<<(n4 + 255) / 256, 256>>>(Wis, (__nv_bfloat16*)p_wish, (__nv_bfloat16*)p_wisl, n4);
    }

    // 1) input-side gate GEMMs (mma.sync tensor cores, fwd + bwd)
    mma_gemm_kernel<<<dim3(T_LEN, G4 / 128), 256, SMEM_MMA>>>(
        (const __nv_bfloat16*)p_wifh, (const __nv_bfloat16*)p_wifl,
        (const __nv_bfloat16*)p_xh, (const __nv_bfloat16*)p_xl,
        bf, (float*)p_xf, DIN, 1, 0, G4);
    mma_gemm_kernel<<<dim3(T_LEN, G4 / 128), 256, SMEM_MMA>>>(
        (const __nv_bfloat16*)p_wibh, (const __nv_bfloat16*)p_wibl,
        (const __nv_bfloat16*)p_xh, (const __nv_bfloat16*)p_xl,
        bb, (float*)p_xb, DIN, 1, 1, G4);

    // 2) fwd + bwd recurrent scans (persistent, 128 co-resident CTAs)
    scan_fb_kernel<<<128, 256, SMEM_FB>>>(Whf, Whb);

    // 3) transpose+split histories, then combiner input GEMM (tensor cores)
    transpose_comb_kernel<<<dim3(T_LEN, HID2 / 64), 256>>>();
    mma_gemm_kernel<<<dim3(T_LEN, G8 / 128), 256, SMEM_MMA>>>(
        (const __nv_bfloat16*)p_wish, (const __nv_bfloat16*)p_wisl,
        (const __nv_bfloat16*)p_cth, (const __nv_bfloat16*)p_ctl,
        bs, (float*)p_xs, HID2, 0, 0, G8);

    // 4) combiner recurrent scan
    scan_comb_kernel<<<128, 256, SMEM_COMB>>>(Whs);

    // 5) output head
    head_kernel<<<1, 128>>>(Wo, bo, out);
}